// round 11
// baseline (speedup 1.0000x reference)
#include <cuda_runtime.h>
#include <cuda_bf16.h>
#include <stdint.h>
#include <math.h>

#define B_N 4096
#define D_N 2048
#define C_N 64

#define BT 128            // CTA tile M = N = 128
#define BKS 64            // K per stage (bf16 elems) = 128 bytes per row
#define STAGES 3
#define A_TILE_B (BT*128)               // 16384 bytes
#define STAGE_B  (2*A_TILE_B)           // 32768 bytes
#define SMEM_TOTAL (1024 + STAGES*STAGE_B)   // 99328
#define TPAD 136          // transposed-bounce row stride (bf16 elems)

// mega-kernel bid regions
#define PREPX_BLOCKS 128
#define G1_OFF  PREPX_BLOCKS
#define G1_BLOCKS 1024    // 32x32 triangular (empties exit)
#define G2_OFF  (G1_OFF + G1_BLOCKS)       // 1152
#define G2_BLOCKS 512     // 32 (m) x 16 (n)
#define MIX_OFF (G2_OFF + G2_BLOCKS)       // 1664
#define MIX_BLOCKS 512    // 32 (row blk) x 16 (col blk)
#define TOTAL_BLOCKS (MIX_OFF + MIX_BLOCKS)  // 2176

// ---------------- scratch (static device globals) ----------------
__device__ __align__(128) __nv_bfloat16 g_xbf[B_N * D_N];            // 16 MB
__device__ __align__(128) __nv_bfloat16 g_xT[D_N * B_N];             // 16 MB
__device__ __align__(128) __nv_bfloat16 g_expSbf[(size_t)B_N * B_N]; // 32 MB
__device__ __align__(128) float g_R[B_N * D_N];                      // 32 MB
__device__ float g_rowsum[B_N];
__device__ float g_keep[B_N];
__device__ float g_contrib[B_N];
__device__ int   g_cntX[32];     // prepx readiness (4 per 128-row block)
__device__ int   g_cnt[32];      // GEMM1 row-block readiness (32 per block)
__device__ int   g_cnt2[16];     // GEMM2 column-block readiness (32 per block)
__device__ int   g_tdone[1024];  // per expS 128x128 tile done flags [row*32+col]

// ---------------- PTX helpers (sm_80+ generic ISA only) ----------------
__device__ __forceinline__ uint32_t smem_u32(const void* p) {
    uint32_t a;
    asm("{ .reg .u64 t; cvta.to.shared.u64 t, %1; cvt.u32.u64 %0, t; }" : "=r"(a) : "l"(p));
    return a;
}
__device__ __forceinline__ void cp16(uint32_t s, const void* g) {
    asm volatile("cp.async.cg.shared.global [%0], [%1], 16;" :: "r"(s), "l"(g));
}
__device__ __forceinline__ void cp_commit() { asm volatile("cp.async.commit_group;"); }
__device__ __forceinline__ void cp_wait1()  { asm volatile("cp.async.wait_group 1;"); }

__device__ __forceinline__ void ldsm4(uint32_t* r, uint32_t addr) {
    asm volatile("ldmatrix.sync.aligned.m8n8.x4.shared.b16 {%0,%1,%2,%3}, [%4];"
        : "=r"(r[0]), "=r"(r[1]), "=r"(r[2]), "=r"(r[3]) : "r"(addr));
}
__device__ __forceinline__ void mma_bf16(float* c, const uint32_t* a, uint32_t b0, uint32_t b1) {
    asm volatile(
        "mma.sync.aligned.m16n8k16.row.col.f32.bf16.bf16.f32 "
        "{%0,%1,%2,%3}, {%4,%5,%6,%7}, {%8,%9}, {%0,%1,%2,%3};"
        : "+f"(c[0]), "+f"(c[1]), "+f"(c[2]), "+f"(c[3])
        : "r"(a[0]), "r"(a[1]), "r"(a[2]), "r"(a[3]), "r"(b0), "r"(b1));
}
__device__ __forceinline__ uint32_t ld_acq(const int* p) {
    uint32_t v;
    asm volatile("ld.acquire.gpu.global.u32 %0, [%1];" : "=r"(v) : "l"(p) : "memory");
    return v;
}

// ---------------- launch 1: per-sample prep + counter reset + y_mix ----------------
__global__ void k_pre(const int* __restrict__ y, const float* __restrict__ c,
                      const int* __restrict__ fs, const float* __restrict__ alpha,
                      const int* __restrict__ beta, float* __restrict__ out) {
    if (blockIdx.x < 16) {
        int i = blockIdx.x * 256 + threadIdx.x;
        int cls = y[i];
        g_contrib[i] = c[cls];
        g_keep[i] = fs[cls] ? 0.0f : 1.0f;
        g_rowsum[i] = 0.0f;
        if (i < 32) { g_cntX[i] = 0; g_cnt[i] = 0; }
        if (i < 16) g_cnt2[i] = 0;
        if (i < 1024) g_tdone[i] = 0;
    } else {
        int idx = (blockIdx.x - 16) * 256 + threadIdx.x;   // over B*C
        int i = idx >> 6;
        int k = idx & 63;
        float a = alpha[i];
        int bi = beta[i];
        float v = a * (k == y[i] ? 1.0f : 0.0f) + (1.0f - a) * (k == y[bi] ? 1.0f : 0.0f);
        out[(size_t)B_N * D_N + idx] = v;
    }
}

// ---------------- launch 2: mega-kernel (prepx + GEMM1 + GEMM2 + mix) ----------------
__global__ __launch_bounds__(256, 2) void k_mega(const float* __restrict__ x,
                                                 const float* __restrict__ alpha,
                                                 const int* __restrict__ beta,
                                                 float* __restrict__ out) {
    const int bid = blockIdx.x;
    const int t = threadIdx.x;
    extern __shared__ char smem[];

    // ======== region 0: prepx (LayerNorm -> g_xbf, transpose -> g_xT) ========
    if (bid < PREPX_BLOCKS) {
        float* mus = reinterpret_cast<float*>(smem);
        float* scs = mus + 32;
        float (*tile)[33] = reinterpret_cast<float(*)[33]>(scs + 32);
        const int row0 = bid * 32;
        const int wid = t >> 5, lane = t & 31;

        #pragma unroll
        for (int rr = 0; rr < 4; rr++) {
            int r = wid * 4 + rr;
            const float* xr = x + (size_t)(row0 + r) * D_N;
            float s = 0.f, s2 = 0.f;
            for (int d = lane; d < D_N; d += 32) {
                float v = xr[d];
                s += v; s2 += v * v;
            }
            #pragma unroll
            for (int o = 16; o > 0; o >>= 1) {
                s  += __shfl_down_sync(0xffffffffu, s, o);
                s2 += __shfl_down_sync(0xffffffffu, s2, o);
            }
            if (lane == 0) {
                float mu = s / (float)D_N;
                float var = s2 / (float)D_N - mu * mu;
                mus[r] = mu;
                scs[r] = rsqrtf(var + 1e-5f) * rsqrtf((float)D_N);
            }
        }
        __syncthreads();

        const int tx = t & 31, ty = t >> 5;
        for (int ct = 0; ct < D_N / 32; ct++) {
            int c0 = ct * 32;
            #pragma unroll
            for (int i = 0; i < 32; i += 8) {
                int r = ty + i;
                float v = x[(size_t)(row0 + r) * D_N + c0 + tx];
                tile[r][tx] = v;
                g_xbf[(size_t)(row0 + r) * D_N + c0 + tx] =
                    __float2bfloat16((v - mus[r]) * scs[r]);
            }
            __syncthreads();
            #pragma unroll
            for (int i = 0; i < 32; i += 8)
                g_xT[(size_t)(c0 + ty + i) * B_N + row0 + tx] = __float2bfloat16(tile[tx][ty + i]);
            __syncthreads();
        }
        __threadfence();
        __syncthreads();
        if (t == 0) atomicAdd(&g_cntX[bid >> 2], 1);
        return;
    }

    // ======== region 3: x_mix (waits on GEMM2 column-block counters) ========
    if (bid >= MIX_OFF) {
        const int q = bid - MIX_OFF;
        const int mr = q >> 4, nb = q & 15;
        while (ld_acq(&g_cnt2[nb]) < 32) __nanosleep(256);
        const int wid = t >> 5, lane = t & 31;
        const int c = nb * 128 + lane * 4;
        #pragma unroll 4
        for (int rr = 0; rr < 16; rr++) {
            int r = mr * 128 + wid * 16 + rr;
            float a = alpha[r];
            float na = 1.0f - a;
            int bi = beta[r];
            float4 r1 = *reinterpret_cast<const float4*>(g_R + (size_t)r * D_N + c);
            float4 r2 = *reinterpret_cast<const float4*>(g_R + (size_t)bi * D_N + c);
            float4 o;
            o.x = a * r1.x + na * r2.x;
            o.y = a * r1.y + na * r2.y;
            o.z = a * r1.z + na * r2.z;
            o.w = a * r1.w + na * r2.w;
            *reinterpret_cast<float4*>(out + (size_t)r * D_N + c) = o;
        }
        return;
    }

    // ======== regions 1+2: GEMM1 (triangular) / GEMM2 ========
    const bool g1 = bid < G2_OFF;
    int bm, bn, KTOT;
    const __nv_bfloat16 *A, *Bmat;
    if (g1) {
        int b1 = bid - G1_OFF;
        bm = b1 >> 5; bn = b1 & 31;
        if (bn < bm) return;                 // symmetry: upper triangle only
        KTOT = D_N; A = g_xbf; Bmat = g_xbf;
        if (t == 0) {
            while (ld_acq(&g_cntX[bm]) < 4) __nanosleep(128);
            while (ld_acq(&g_cntX[bn]) < 4) __nanosleep(128);
        }
        __syncthreads();
    } else {
        int b2 = bid - G2_OFF;
        bm = b2 >> 4; bn = b2 & 15;          // m-major
        KTOT = B_N; A = g_expSbf; Bmat = g_xT;
        // fine-grained: wait only for expS tile (bm, 0) before the prologue loads
        while (ld_acq(&g_tdone[bm * 32]) == 0) __nanosleep(128);
    }

    const uint32_t smem_raw = smem_u32(smem);
    const uint32_t tiles0 = (smem_raw + 1023u) & ~1023u;
    const int wid = t >> 5, lane = t & 31;
    const int KC = KTOT / BKS;

    const int warp_m0 = (wid >> 2) * 64;
    const int warp_n0 = (wid & 3) * 32;
    const int rowA0 = bm * BT;
    const int rowB0 = bn * BT;

    uint32_t sA[STAGES], sB[STAGES];
    #pragma unroll
    for (int s = 0; s < STAGES; s++) {
        sA[s] = tiles0 + (uint32_t)s * STAGE_B;
        sB[s] = sA[s] + A_TILE_B;
    }

    const int lr0 = t >> 3;
    const int cc = t & 7;

    const __nv_bfloat16* gA = A    + (size_t)(rowA0 + lr0) * KTOT + cc * 8;
    const __nv_bfloat16* gB = Bmat + (size_t)(rowB0 + lr0) * KTOT + cc * 8;

    #define LOAD_STAGE(sidx, k0elem) do {                                              \
        _Pragma("unroll")                                                              \
        for (int _i = 0; _i < 4; _i++) {                                               \
            int _lr = lr0 + _i * 32;                                                   \
            uint32_t _soff = (uint32_t)(_lr * 128 + ((cc ^ (_lr & 7)) * 16));          \
            cp16(sA[sidx] + _soff, gA + (size_t)_i * 32 * KTOT + (k0elem));            \
            cp16(sB[sidx] + _soff, gB + (size_t)_i * 32 * KTOT + (k0elem));            \
        }                                                                              \
    } while (0)

    #pragma unroll
    for (int p = 0; p < STAGES - 1; p++) {
        LOAD_STAGE(p, p * BKS);
        cp_commit();
    }

    float acc[4][4][4];
    #pragma unroll
    for (int i = 0; i < 4; i++)
        #pragma unroll
        for (int j = 0; j < 4; j++)
            #pragma unroll
            for (int r = 0; r < 4; r++) acc[i][j][r] = 0.f;

    const int lrow = lane & 15;
    const int lhal = lane >> 4;
    uint32_t aoff[4], boff[2];
    #pragma unroll
    for (int im = 0; im < 4; im++) {
        int r = warp_m0 + im * 16 + lrow;
        aoff[im] = (uint32_t)(r * 128 + ((lhal ^ (r & 7)) << 4));
    }
    #pragma unroll
    for (int ib = 0; ib < 2; ib++) {
        int r = warp_n0 + ib * 16 + lrow;
        boff[ib] = (uint32_t)(r * 128 + ((lhal ^ (r & 7)) << 4));
    }

    for (int c = 0; c < KC; c++) {
        cp_wait1();
        __syncthreads();
        const int p = c + STAGES - 1;
        if (p < KC) {
            // GEMM2: before loading a new 128-row K-block of expS, wait for its tile flag
            if (!g1 && (p & 1) == 0) {
                const int kb = p >> 1;
                while (ld_acq(&g_tdone[bm * 32 + kb]) == 0) __nanosleep(64);
            }
            LOAD_STAGE(p % STAGES, p * BKS);
        }
        cp_commit();

        const uint32_t bufA = sA[c % STAGES];
        const uint32_t bufB = sB[c % STAGES];
        uint32_t aBase[4], bBase[2];
        #pragma unroll
        for (int im = 0; im < 4; im++) aBase[im] = bufA + aoff[im];
        #pragma unroll
        for (int ib = 0; ib < 2; ib++) bBase[ib] = bufB + boff[ib];

        #pragma unroll
        for (int kk = 0; kk < 4; kk++) {
            uint32_t a[4][4], b[2][4];
            #pragma unroll
            for (int im = 0; im < 4; im++)
                ldsm4(a[im], aBase[im] ^ (uint32_t)(kk << 5));
            #pragma unroll
            for (int ib = 0; ib < 2; ib++)
                ldsm4(b[ib], bBase[ib] ^ (uint32_t)(kk << 5));
            #pragma unroll
            for (int im = 0; im < 4; im++) {
                #pragma unroll
                for (int ib = 0; ib < 2; ib++) {
                    mma_bf16(acc[im][ib * 2 + 0], a[im], b[ib][0], b[ib][2]);
                    mma_bf16(acc[im][ib * 2 + 1], a[im], b[ib][1], b[ib][3]);
                }
            }
        }
    }

    // ---- epilogue ----
    const int lq = lane >> 2;
    const int lp = lane & 3;
    int colg[4];
    #pragma unroll
    for (int j = 0; j < 4; j++)
        colg[j] = rowB0 + warp_n0 + (j >> 1) * 16 + (j & 1) * 8 + 2 * lp;

    if (g1) {
        const bool diag = (bm == bn);
        __syncthreads();   // stage buffers dead; reuse as transpose bounce
        __nv_bfloat16* tsm = reinterpret_cast<__nv_bfloat16*>(smem + (tiles0 - smem_raw));

        float kp0[4], kp1[4];
        #pragma unroll
        for (int j = 0; j < 4; j++) { kp0[j] = g_keep[colg[j]]; kp1[j] = g_keep[colg[j] + 1]; }
        float cs[8];
        #pragma unroll
        for (int k2 = 0; k2 < 8; k2++) cs[k2] = 0.f;

        #pragma unroll
        for (int im = 0; im < 4; im++) {
            #pragma unroll
            for (int h = 0; h < 2; h++) {
                int row = rowA0 + warp_m0 + im * 16 + h * 8 + lq;
                float kr = g_keep[row];
                float rs = 0.f;
                #pragma unroll
                for (int j = 0; j < 4; j++) {
                    int c0 = colg[j], c1 = c0 + 1;
                    float e0 = __expf(acc[im][j][2 * h + 0]);
                    float e1 = __expf(acc[im][j][2 * h + 1]);
                    float v0 = (c0 == row ? 0.f : kp0[j]) * e0;
                    float v1 = (c1 == row ? 0.f : kp1[j]) * e1;
                    __nv_bfloat16 b0 = __float2bfloat16(v0);
                    __nv_bfloat16 b1 = __float2bfloat16(v1);
                    rs += __bfloat162float(b0) + __bfloat162float(b1);
                    __nv_bfloat162 p2(b0, b1);
                    *reinterpret_cast<uint32_t*>(g_expSbf + (size_t)row * B_N + c0) =
                        *reinterpret_cast<uint32_t*>(&p2);
                    if (!diag) {
                        float t0f = (c0 == row ? 0.f : kr) * e0;
                        float t1f = (c1 == row ? 0.f : kr) * e1;
                        __nv_bfloat16 t0 = __float2bfloat16(t0f);
                        __nv_bfloat16 t1 = __float2bfloat16(t1f);
                        cs[2 * j]     += __bfloat162float(t0);
                        cs[2 * j + 1] += __bfloat162float(t1);
                        int rl = row - rowA0;
                        tsm[(c0 - rowB0) * TPAD + rl] = t0;
                        tsm[(c1 - rowB0) * TPAD + rl] = t1;
                    }
                }
                rs += __shfl_xor_sync(0xffffffffu, rs, 1);
                rs += __shfl_xor_sync(0xffffffffu, rs, 2);
                if (lp == 0) atomicAdd(&g_rowsum[row], rs);
            }
        }

        if (!diag) {
            #pragma unroll
            for (int k2 = 0; k2 < 8; k2++) {
                cs[k2] += __shfl_xor_sync(0xffffffffu, cs[k2], 4);
                cs[k2] += __shfl_xor_sync(0xffffffffu, cs[k2], 8);
                cs[k2] += __shfl_xor_sync(0xffffffffu, cs[k2], 16);
            }
            if (lane < 4) {
                #pragma unroll
                for (int j = 0; j < 4; j++) {
                    atomicAdd(&g_rowsum[colg[j]],     cs[2 * j]);
                    atomicAdd(&g_rowsum[colg[j] + 1], cs[2 * j + 1]);
                }
            }
            __syncthreads();
            const int cl0 = t >> 4;
            const int ch = t & 15;
            #pragma unroll
            for (int it = 0; it < 8; it++) {
                int cl = cl0 + it * 16;
                uint4 v = *reinterpret_cast<const uint4*>(tsm + cl * TPAD + ch * 8);
                *reinterpret_cast<uint4*>(g_expSbf + (size_t)(rowB0 + cl) * B_N + rowA0 + ch * 8) = v;
            }
        }

        // release: counters first, then per-tile flags (flag observes => cnt done)
        __threadfence();
        __syncthreads();
        if (t == 0) {
            atomicAdd(&g_cnt[bm], 1);
            if (bm != bn) atomicAdd(&g_cnt[bn], 1);
            atomicExch(&g_tdone[bm * 32 + bn], 1);
            if (bm != bn) atomicExch(&g_tdone[bn * 32 + bm], 1);
        }
    } else {
        // rowsum completeness guard (normally already satisfied via tile flags)
        while (ld_acq(&g_cnt[bm]) < 32) __nanosleep(64);
        #pragma unroll
        for (int im = 0; im < 4; im++) {
            #pragma unroll
            for (int h = 0; h < 2; h++) {
                int row = rowA0 + warp_m0 + im * 16 + h * 8 + lq;
                float ct = g_contrib[row];
                float s1 = ct / g_rowsum[row];     // fused reciprocal
                float s2 = 1.0f - ct;
                #pragma unroll
                for (int j = 0; j < 4; j++) {
                    const float2 xv = *(const float2*)(x + (size_t)row * D_N + colg[j]);
                    float2 o;
                    o.x = acc[im][j][2 * h + 0] * s1 + xv.x * s2;
                    o.y = acc[im][j][2 * h + 1] * s1 + xv.y * s2;
                    *(float2*)(g_R + (size_t)row * D_N + colg[j]) = o;
                }
            }
        }
        __threadfence();
        __syncthreads();
        if (t == 0) atomicAdd(&g_cnt2[bn], 1);
    }
    #undef LOAD_STAGE
}

extern "C" void kernel_launch(void* const* d_in, const int* in_sizes, int n_in,
                              void* d_out, int out_size) {
    const float* x     = (const float*)d_in[0];
    const int*   y     = (const int*)  d_in[1];
    const float* alpha = (const float*)d_in[2];
    const int*   beta  = (const int*)  d_in[3];
    const float* c     = (const float*)d_in[4];
    const int*   fs    = (const int*)  d_in[5];
    float* out = (float*)d_out;

    cudaFuncSetAttribute(k_mega, cudaFuncAttributeMaxDynamicSharedMemorySize, SMEM_TOTAL);

    k_pre<<<16 + (B_N * C_N) / 256, 256>>>(y, c, fs, alpha, beta, out);
    k_mega<<<TOTAL_BLOCKS, 256, SMEM_TOTAL>>>(x, alpha, beta, out);
}

// round 12
// speedup vs baseline: 1.0763x; 1.0763x over previous
#include <cuda_runtime.h>
#include <cuda_bf16.h>
#include <cuda_fp8.h>
#include <stdint.h>
#include <math.h>

#define B_N 4096
#define D_N 2048
#define C_N 64

#define BT 128            // CTA tile M = N = 128
#define STAGES 3
#define A_TILE_B (BT*128)               // 16384 bytes (128 rows x 128B)
#define STAGE_B  (2*A_TILE_B)           // 32768 bytes
#define SMEM_TOTAL (1024 + STAGES*STAGE_B)   // 99328
#define TPAD 136          // transposed-bounce row stride (bf16 elems)

#define G1_BLOCKS 1024    // 32x32 triangular (empties exit)
#define G2_BLOCKS 512     // 32 (m) x 16 (n)

// ---------------- scratch (static device globals) ----------------
__device__ __align__(128) unsigned char  g_x8[B_N * D_N];            //  8 MB e4m3(32*x_norm)
__device__ __align__(128) __nv_bfloat16 g_xT[D_N * B_N];             // 16 MB bf16 x^T
__device__ __align__(128) __nv_bfloat16 g_expSbf[(size_t)B_N * B_N]; // 32 MB
__device__ __align__(128) float g_R[B_N * D_N];                      // 32 MB
__device__ float g_rowsum[B_N];
__device__ float g_keep[B_N];
__device__ float g_contrib[B_N];
__device__ int   g_cnt[32];          // GEMM1 row-block readiness counters

// ---------------- PTX helpers (plain sm_80/sm_89 ISA only) ----------------
__device__ __forceinline__ uint32_t smem_u32(const void* p) {
    uint32_t a;
    asm("{ .reg .u64 t; cvta.to.shared.u64 t, %1; cvt.u32.u64 %0, t; }" : "=r"(a) : "l"(p));
    return a;
}
__device__ __forceinline__ void cp16(uint32_t s, const void* g) {
    asm volatile("cp.async.cg.shared.global [%0], [%1], 16;" :: "r"(s), "l"(g));
}
__device__ __forceinline__ void cp_commit() { asm volatile("cp.async.commit_group;"); }
__device__ __forceinline__ void cp_wait1()  { asm volatile("cp.async.wait_group 1;"); }

__device__ __forceinline__ void ldsm4(uint32_t* r, uint32_t addr) {
    asm volatile("ldmatrix.sync.aligned.m8n8.x4.shared.b16 {%0,%1,%2,%3}, [%4];"
        : "=r"(r[0]), "=r"(r[1]), "=r"(r[2]), "=r"(r[3]) : "r"(addr));
}
__device__ __forceinline__ void mma_bf16(float* c, const uint32_t* a, uint32_t b0, uint32_t b1) {
    asm volatile(
        "mma.sync.aligned.m16n8k16.row.col.f32.bf16.bf16.f32 "
        "{%0,%1,%2,%3}, {%4,%5,%6,%7}, {%8,%9}, {%0,%1,%2,%3};"
        : "+f"(c[0]), "+f"(c[1]), "+f"(c[2]), "+f"(c[3])
        : "r"(a[0]), "r"(a[1]), "r"(a[2]), "r"(a[3]), "r"(b0), "r"(b1));
}
__device__ __forceinline__ void mma_e4m3(float* c, const uint32_t* a, uint32_t b0, uint32_t b1) {
    asm volatile(
        "mma.sync.aligned.m16n8k32.row.col.f32.e4m3.e4m3.f32 "
        "{%0,%1,%2,%3}, {%4,%5,%6,%7}, {%8,%9}, {%0,%1,%2,%3};"
        : "+f"(c[0]), "+f"(c[1]), "+f"(c[2]), "+f"(c[3])
        : "r"(a[0]), "r"(a[1]), "r"(a[2]), "r"(a[3]), "r"(b0), "r"(b1));
}
__device__ __forceinline__ uint32_t ld_acq(const int* p) {
    uint32_t v;
    asm volatile("ld.acquire.gpu.global.u32 %0, [%1];" : "=r"(v) : "l"(p) : "memory");
    return v;
}

// ---------------- small kernels ----------------
__global__ void k_prep(const int* __restrict__ y, const float* __restrict__ c,
                       const int* __restrict__ fs) {
    int i = blockIdx.x * blockDim.x + threadIdx.x;
    if (i < B_N) {
        int cls = y[i];
        g_contrib[i] = c[cls];
        g_keep[i] = fs[cls] ? 0.0f : 1.0f;
        g_rowsum[i] = 0.0f;
        if (i < 32) g_cnt[i] = 0;
    }
}

// fused: LayerNorm*32 -> g_x8 (e4m3)  AND  raw-x transpose -> g_xT (bf16)
__global__ __launch_bounds__(256) void k_prepx(const float* __restrict__ x) {
    __shared__ float mus[32], scs[32];
    __shared__ float tile[32][33];
    const int row0 = blockIdx.x * 32;
    const int wid = threadIdx.x >> 5, lane = threadIdx.x & 31;

    #pragma unroll
    for (int rr = 0; rr < 4; rr++) {
        int r = wid * 4 + rr;
        const float* xr = x + (size_t)(row0 + r) * D_N;
        float s = 0.f, s2 = 0.f;
        for (int d = lane; d < D_N; d += 32) {
            float v = xr[d];
            s += v; s2 += v * v;
        }
        #pragma unroll
        for (int o = 16; o > 0; o >>= 1) {
            s  += __shfl_down_sync(0xffffffffu, s, o);
            s2 += __shfl_down_sync(0xffffffffu, s2, o);
        }
        if (lane == 0) {
            float mu = s / (float)D_N;
            float var = s2 / (float)D_N - mu * mu;
            mus[r] = mu;
            scs[r] = rsqrtf(var + 1e-5f) * rsqrtf((float)D_N) * 32.0f;  // x_norm scaled by 32
        }
    }
    __syncthreads();

    const int tx = threadIdx.x & 31, ty = threadIdx.x >> 5;
    for (int ct = 0; ct < D_N / 32; ct++) {
        int c0 = ct * 32;
        #pragma unroll
        for (int i = 0; i < 32; i += 8) {
            int r = ty + i;
            float v = x[(size_t)(row0 + r) * D_N + c0 + tx];
            tile[r][tx] = v;
            float q = (v - mus[r]) * scs[r];
            g_x8[(size_t)(row0 + r) * D_N + c0 + tx] =
                (unsigned char)__nv_cvt_float_to_fp8(q, __NV_SATFINITE, __NV_E4M3);
        }
        __syncthreads();
        #pragma unroll
        for (int i = 0; i < 32; i += 8)
            g_xT[(size_t)(c0 + ty + i) * B_N + row0 + tx] = __float2bfloat16(tile[tx][ty + i]);
        __syncthreads();
    }
}

// ---------------- shared GEMM mainloop (byte-addressed, dtype-templated) ----------------
// 128-row tiles, 128B K-chunks per stage. FP8: each 128B row = K128 e4m3 (4x k32 mma).
// BF16: each 128B row = K64 bf16 (4x k16 mma). Identical ldsm/swizzle structure.
template<bool FP8, int ROWB, int KC>
__device__ __forceinline__ void gemm_main(
    const char* __restrict__ Abase, const char* __restrict__ Bbase,
    const uint32_t* sA, const uint32_t* sB,
    float acc[4][4][4],
    const uint32_t* aoff, const uint32_t* boff,
    int lr0, int cc)
{
    #define LD(sidx, chunk) do {                                                       \
        _Pragma("unroll")                                                              \
        for (int _i = 0; _i < 4; _i++) {                                               \
            int _lr = lr0 + _i * 32;                                                   \
            uint32_t _soff = (uint32_t)(_lr * 128 + ((cc ^ (_lr & 7)) * 16));          \
            cp16(sA[sidx] + _soff, Abase + (size_t)_lr * ROWB + (chunk) * 128 + cc * 16); \
            cp16(sB[sidx] + _soff, Bbase + (size_t)_lr * ROWB + (chunk) * 128 + cc * 16); \
        }                                                                              \
    } while (0)

    #pragma unroll
    for (int p = 0; p < STAGES - 1; p++) {
        LD(p, p);
        cp_commit();
    }

    for (int c = 0; c < KC; c++) {
        cp_wait1();
        __syncthreads();
        if (c + STAGES - 1 < KC) LD((c + STAGES - 1) % STAGES, c + STAGES - 1);
        cp_commit();

        const uint32_t bufA = sA[c % STAGES];
        const uint32_t bufB = sB[c % STAGES];
        uint32_t aBase[4], bBase[2];
        #pragma unroll
        for (int im = 0; im < 4; im++) aBase[im] = bufA + aoff[im];
        #pragma unroll
        for (int ib = 0; ib < 2; ib++) bBase[ib] = bufB + boff[ib];

        #pragma unroll
        for (int kk = 0; kk < 4; kk++) {
            uint32_t a[4][4], b[2][4];
            #pragma unroll
            for (int im = 0; im < 4; im++)
                ldsm4(a[im], aBase[im] ^ (uint32_t)(kk << 5));
            #pragma unroll
            for (int ib = 0; ib < 2; ib++)
                ldsm4(b[ib], bBase[ib] ^ (uint32_t)(kk << 5));
            #pragma unroll
            for (int im = 0; im < 4; im++) {
                #pragma unroll
                for (int ib = 0; ib < 2; ib++) {
                    if (FP8) {
                        mma_e4m3(acc[im][ib * 2 + 0], a[im], b[ib][0], b[ib][2]);
                        mma_e4m3(acc[im][ib * 2 + 1], a[im], b[ib][1], b[ib][3]);
                    } else {
                        mma_bf16(acc[im][ib * 2 + 0], a[im], b[ib][0], b[ib][2]);
                        mma_bf16(acc[im][ib * 2 + 1], a[im], b[ib][1], b[ib][3]);
                    }
                }
            }
        }
    }
    #undef LD
}

// ---------------- fused GEMM1 (fp8, triangular) + GEMM2 (bf16), one launch ----------------
__global__ __launch_bounds__(256, 2) void k_fused(const float* __restrict__ x) {
    const int bid = blockIdx.x;
    const bool g1 = bid < G1_BLOCKS;
    int bm, bn;
    if (g1) {
        bm = bid >> 5; bn = bid & 31;
        if (bn < bm) return;                 // symmetry: upper triangle only
    } else {
        int b2 = bid - G1_BLOCKS;
        bm = b2 >> 4; bn = b2 & 15;          // m-major
        if (threadIdx.x == 0) {
            while (ld_acq(&g_cnt[bm]) < 32) __nanosleep(256);
        }
        __syncthreads();
    }

    extern __shared__ char smem[];
    const uint32_t smem_raw = smem_u32(smem);
    const uint32_t tiles0 = (smem_raw + 1023u) & ~1023u;
    const int t = threadIdx.x;
    const int wid = t >> 5, lane = t & 31;

    const int warp_m0 = (wid >> 2) * 64;
    const int warp_n0 = (wid & 3) * 32;
    const int rowA0 = bm * BT;
    const int rowB0 = bn * BT;

    uint32_t sA[STAGES], sB[STAGES];
    #pragma unroll
    for (int s = 0; s < STAGES; s++) {
        sA[s] = tiles0 + (uint32_t)s * STAGE_B;
        sB[s] = sA[s] + A_TILE_B;
    }

    const int lr0 = t >> 3;
    const int cc = t & 7;

    float acc[4][4][4];
    #pragma unroll
    for (int i = 0; i < 4; i++)
        #pragma unroll
        for (int j = 0; j < 4; j++)
            #pragma unroll
            for (int r = 0; r < 4; r++) acc[i][j][r] = 0.f;

    const int lrow = lane & 15;
    const int lhal = lane >> 4;
    uint32_t aoff[4], boff[2];
    #pragma unroll
    for (int im = 0; im < 4; im++) {
        int r = warp_m0 + im * 16 + lrow;
        aoff[im] = (uint32_t)(r * 128 + ((lhal ^ (r & 7)) << 4));
    }
    #pragma unroll
    for (int ib = 0; ib < 2; ib++) {
        int r = warp_n0 + ib * 16 + lrow;
        boff[ib] = (uint32_t)(r * 128 + ((lhal ^ (r & 7)) << 4));
    }

    if (g1) {
        // A = B = g_x8 (e4m3, row = 2048 B), K = 2048 -> KC = 16
        gemm_main<true, D_N, D_N / 128>(
            (const char*)g_x8 + (size_t)rowA0 * D_N,
            (const char*)g_x8 + (size_t)rowB0 * D_N,
            sA, sB, acc, aoff, boff, lr0, cc);
    } else {
        // A = expS (bf16, row = 8192 B), B = xT (bf16), K = 4096 -> KC = 64
        gemm_main<false, 2 * B_N, (2 * B_N) / 128>(
            (const char*)g_expSbf + (size_t)rowA0 * 2 * B_N,
            (const char*)g_xT + (size_t)rowB0 * 2 * B_N,
            sA, sB, acc, aoff, boff, lr0, cc);
    }

    // ---- epilogue ----
    const int lq = lane >> 2;
    const int lp = lane & 3;
    int colg[4];
    #pragma unroll
    for (int j = 0; j < 4; j++)
        colg[j] = rowB0 + warp_n0 + (j >> 1) * 16 + (j & 1) * 8 + 2 * lp;

    if (g1) {
        const bool diag = (bm == bn);
        const float ksc = 1.0f / 1024.0f;     // undo (32)^2 input scaling
        __syncthreads();   // stage buffers dead; reuse as transpose bounce
        __nv_bfloat16* tsm = reinterpret_cast<__nv_bfloat16*>(smem + (tiles0 - smem_raw));

        float kp0[4], kp1[4];
        #pragma unroll
        for (int j = 0; j < 4; j++) { kp0[j] = g_keep[colg[j]]; kp1[j] = g_keep[colg[j] + 1]; }
        float cs[8];
        #pragma unroll
        for (int k2 = 0; k2 < 8; k2++) cs[k2] = 0.f;

        #pragma unroll
        for (int im = 0; im < 4; im++) {
            #pragma unroll
            for (int h = 0; h < 2; h++) {
                int row = rowA0 + warp_m0 + im * 16 + h * 8 + lq;
                float kr = g_keep[row];
                float rs = 0.f;
                #pragma unroll
                for (int j = 0; j < 4; j++) {
                    int c0 = colg[j], c1 = c0 + 1;
                    float e0 = __expf(acc[im][j][2 * h + 0] * ksc);
                    float e1 = __expf(acc[im][j][2 * h + 1] * ksc);
                    float v0 = (c0 == row ? 0.f : kp0[j]) * e0;
                    float v1 = (c1 == row ? 0.f : kp1[j]) * e1;
                    __nv_bfloat16 b0 = __float2bfloat16(v0);
                    __nv_bfloat16 b1 = __float2bfloat16(v1);
                    rs += __bfloat162float(b0) + __bfloat162float(b1);
                    __nv_bfloat162 p2(b0, b1);
                    *reinterpret_cast<uint32_t*>(g_expSbf + (size_t)row * B_N + c0) =
                        *reinterpret_cast<uint32_t*>(&p2);
                    if (!diag) {
                        float t0f = (c0 == row ? 0.f : kr) * e0;
                        float t1f = (c1 == row ? 0.f : kr) * e1;
                        __nv_bfloat16 t0 = __float2bfloat16(t0f);
                        __nv_bfloat16 t1 = __float2bfloat16(t1f);
                        cs[2 * j]     += __bfloat162float(t0);
                        cs[2 * j + 1] += __bfloat162float(t1);
                        int rl = row - rowA0;
                        tsm[(c0 - rowB0) * TPAD + rl] = t0;
                        tsm[(c1 - rowB0) * TPAD + rl] = t1;
                    }
                }
                rs += __shfl_xor_sync(0xffffffffu, rs, 1);
                rs += __shfl_xor_sync(0xffffffffu, rs, 2);
                if (lp == 0) atomicAdd(&g_rowsum[row], rs);
            }
        }

        if (!diag) {
            #pragma unroll
            for (int k2 = 0; k2 < 8; k2++) {
                cs[k2] += __shfl_xor_sync(0xffffffffu, cs[k2], 4);
                cs[k2] += __shfl_xor_sync(0xffffffffu, cs[k2], 8);
                cs[k2] += __shfl_xor_sync(0xffffffffu, cs[k2], 16);
            }
            if (lane < 4) {
                #pragma unroll
                for (int j = 0; j < 4; j++) {
                    atomicAdd(&g_rowsum[colg[j]],     cs[2 * j]);
                    atomicAdd(&g_rowsum[colg[j] + 1], cs[2 * j + 1]);
                }
            }
            __syncthreads();
            const int cl0 = t >> 4;
            const int ch = t & 15;
            #pragma unroll
            for (int it = 0; it < 8; it++) {
                int cl = cl0 + it * 16;
                uint4 v = *reinterpret_cast<const uint4*>(tsm + cl * TPAD + ch * 8);
                *reinterpret_cast<uint4*>(g_expSbf + (size_t)(rowB0 + cl) * B_N + rowA0 + ch * 8) = v;
            }
        }

        __threadfence();
        __syncthreads();
        if (t == 0) {
            atomicAdd(&g_cnt[bm], 1);
            if (bm != bn) atomicAdd(&g_cnt[bn], 1);
        }
    } else {
        #pragma unroll
        for (int im = 0; im < 4; im++) {
            #pragma unroll
            for (int h = 0; h < 2; h++) {
                int row = rowA0 + warp_m0 + im * 16 + h * 8 + lq;
                float ct = g_contrib[row];
                float s1 = ct / g_rowsum[row];     // fused reciprocal
                float s2 = 1.0f - ct;
                #pragma unroll
                for (int j = 0; j < 4; j++) {
                    const float2 xv = *(const float2*)(x + (size_t)row * D_N + colg[j]);
                    float2 o;
                    o.x = acc[im][j][2 * h + 0] * s1 + xv.x * s2;
                    o.y = acc[im][j][2 * h + 1] * s1 + xv.y * s2;
                    *(float2*)(g_R + (size_t)row * D_N + colg[j]) = o;
                }
            }
        }
    }
}

// ---------------- mix kernels ----------------
__global__ __launch_bounds__(256) void k_mixx(const float* __restrict__ alpha,
                                              const int* __restrict__ beta,
                                              float* __restrict__ out) {
    int idx = blockIdx.x * blockDim.x + threadIdx.x;
    const int nd4 = D_N / 4;
    if (idx < B_N * nd4) {
        int i = idx / nd4;
        int d4 = idx - i * nd4;
        float a = alpha[i];
        float na = 1.0f - a;
        int bi = beta[i];
        const float4* R4 = (const float4*)g_R;
        float4 r1 = R4[(size_t)i * nd4 + d4];
        float4 r2 = R4[(size_t)bi * nd4 + d4];
        float4 o;
        o.x = a * r1.x + na * r2.x;
        o.y = a * r1.y + na * r2.y;
        o.z = a * r1.z + na * r2.z;
        o.w = a * r1.w + na * r2.w;
        ((float4*)out)[idx] = o;
    }
}

__global__ void k_mixy(const float* __restrict__ alpha,
                       const int* __restrict__ beta,
                       const int* __restrict__ y,
                       float* __restrict__ out) {
    int idx = blockIdx.x * blockDim.x + threadIdx.x;
    if (idx < B_N * C_N) {
        int i = idx / C_N;
        int k = idx - i * C_N;
        float a = alpha[i];
        int bi = beta[i];
        float v = a * (k == y[i] ? 1.0f : 0.0f) + (1.0f - a) * (k == y[bi] ? 1.0f : 0.0f);
        out[(size_t)B_N * D_N + idx] = v;
    }
}

extern "C" void kernel_launch(void* const* d_in, const int* in_sizes, int n_in,
                              void* d_out, int out_size) {
    const float* x     = (const float*)d_in[0];
    const int*   y     = (const int*)  d_in[1];
    const float* alpha = (const float*)d_in[2];
    const int*   beta  = (const int*)  d_in[3];
    const float* c     = (const float*)d_in[4];
    const int*   fs    = (const int*)  d_in[5];
    float* out = (float*)d_out;

    cudaFuncSetAttribute(k_fused, cudaFuncAttributeMaxDynamicSharedMemorySize, SMEM_TOTAL);

    k_prep<<<(B_N + 255) / 256, 256>>>(y, c, fs);
    k_prepx<<<B_N / 32, 256>>>(x);
    k_fused<<<G1_BLOCKS + G2_BLOCKS, 256, SMEM_TOTAL>>>(x);
    k_mixx<<<(B_N * (D_N / 4) + 255) / 256, 256>>>(alpha, beta, out);
    k_mixy<<<(B_N * C_N + 255) / 256, 256>>>(alpha, beta, y, out);
}